// round 14
// baseline (speedup 1.0000x reference)
#include <cuda_runtime.h>
#include <cuda_bf16.h>
#include <cstdint>

#define BB   4
#define CIN  128
#define COUT 256
#define HWSZ 4096
#define PTOT 16384
#define KG   9
#define HID  512
#define KC   1152

// ---------------- threefry2x32 (jax-compatible) ----------------
__host__ __device__ __forceinline__ uint32_t rotl32(uint32_t x, int d) {
    return (x << d) | (x >> (32 - d));
}
__host__ __device__ __forceinline__ void threefry(uint32_t k0, uint32_t k1,
                                                  uint32_t x0, uint32_t x1,
                                                  uint32_t& o0, uint32_t& o1) {
    uint32_t ks2 = k0 ^ k1 ^ 0x1BD11BDAu;
    x0 += k0; x1 += k1;
#define TFR(r) { x0 += x1; x1 = rotl32(x1, r); x1 ^= x0; }
    TFR(13) TFR(15) TFR(26) TFR(6)
    x0 += k1;  x1 += ks2 + 1u;
    TFR(17) TFR(29) TFR(16) TFR(24)
    x0 += ks2; x1 += k0 + 2u;
    TFR(13) TFR(15) TFR(26) TFR(6)
    x0 += k0;  x1 += k1 + 3u;
    TFR(17) TFR(29) TFR(16) TFR(24)
    x0 += k1;  x1 += ks2 + 4u;
    TFR(13) TFR(15) TFR(26) TFR(6)
    x0 += ks2; x1 += k0 + 5u;
#undef TFR
    o0 = x0; o1 = x1;
}

// partitionable-threefry 32-bit sample for flat element i: sample = o0 ^ o1
__device__ __forceinline__ uint32_t jbits32(uint32_t k0, uint32_t k1, uint32_t i) {
    uint32_t o0, o1;
    threefry(k0, k1, 0u, i, o0, o1);
    return o0 ^ o1;
}

// ---------------- baseline-ISA asm helpers ----------------
__device__ __forceinline__ uint32_t smem_u32(const void* p) {
    uint32_t a;
    asm("{ .reg .u64 t; cvta.to.shared.u64 t, %1; cvt.u32.u64 %0, t; }" : "=r"(a) : "l"(p));
    return a;
}
__device__ __forceinline__ void cpa16(uint32_t sa, const void* g) {
    asm volatile("cp.async.cg.shared.global [%0], [%1], 16;" :: "r"(sa), "l"(g));
}
#define CP_COMMIT() asm volatile("cp.async.commit_group;" ::: "memory")
#define CP_WAIT2()  asm volatile("cp.async.wait_group 2;" ::: "memory")
#define CP_WAIT1()  asm volatile("cp.async.wait_group 1;" ::: "memory")
#define CP_WAIT0()  asm volatile("cp.async.wait_group 0;" ::: "memory")

__device__ __forceinline__ void ldsm4(uint32_t* r, uint32_t addr) {
    asm volatile("ldmatrix.sync.aligned.m8n8.x4.shared.b16 {%0,%1,%2,%3}, [%4];"
        : "=r"(r[0]), "=r"(r[1]), "=r"(r[2]), "=r"(r[3]) : "r"(addr));
}
__device__ __forceinline__ void mma_bf16(float* c, const uint32_t* a, uint32_t b0, uint32_t b1) {
    asm volatile("mma.sync.aligned.m16n8k16.row.col.f32.bf16.bf16.f32 "
        "{%0,%1,%2,%3}, {%4,%5,%6,%7}, {%8,%9}, {%0,%1,%2,%3};"
        : "+f"(c[0]), "+f"(c[1]), "+f"(c[2]), "+f"(c[3])
        : "r"(a[0]), "r"(a[1]), "r"(a[2]), "r"(a[3]), "r"(b0), "r"(b1));
}

// ---------------- scratch (device globals; no allocs allowed) ----------------
__device__ float g_xt[BB * HWSZ * CIN];           // x transposed: [b][hw][c]
__device__ float g_hid[PTOT * HID];               // hidden layer
__device__ float g_params[PTOT * 27];             // MLP output
__device__ int   g_flat[PTOT * KG * 8];           // candidate flat indices
__device__ float g_wgt[PTOT * KG * 8];            // candidate weights
__device__ __nv_bfloat16 g_fhi[(size_t)PTOT * KC];  // feat hi (bf16)
__device__ __nv_bfloat16 g_flo[(size_t)PTOT * KC];  // feat lo (bf16)
__device__ __nv_bfloat16 g_whiT[COUT * KC];       // Wu^T hi: [o][q]
__device__ __nv_bfloat16 g_wloT[COUT * KC];       // Wu^T lo: [o][q]

// ---------------- x transpose: (b,c,hw) -> (b,hw,c) ----------------
__global__ void k_transpose(const float* __restrict__ x) {
    __shared__ float tile[32][33];
    int b = blockIdx.z;
    int hw0 = blockIdx.x * 32, c0 = blockIdx.y * 32;
    int tx = threadIdx.x, ty = threadIdx.y;   // 32 x 8
#pragma unroll
    for (int i = 0; i < 4; i++) {
        int c = c0 + ty + i * 8;
        tile[ty + i * 8][tx] = x[(b * CIN + c) * HWSZ + hw0 + tx];
    }
    __syncthreads();
#pragma unroll
    for (int i = 0; i < 4; i++) {
        int hw = hw0 + ty + i * 8;
        g_xt[(b * HWSZ + hw) * CIN + c0 + tx] = tile[tx][ty + i * 8];
    }
}

// ---------------- Wu transpose + bf16 split ----------------
__global__ void k_wuprep(const float* __restrict__ Wu) {
    __shared__ float t[32][33];
    int q0 = blockIdx.x * 32, o0 = blockIdx.y * 32;
    int tx = threadIdx.x, ty = threadIdx.y;   // 32 x 8
#pragma unroll
    for (int i = 0; i < 4; i++)
        t[ty + i * 8][tx] = Wu[(q0 + ty + i * 8) * COUT + o0 + tx];
    __syncthreads();
#pragma unroll
    for (int i = 0; i < 4; i++) {
        int o = o0 + ty + i * 8, q = q0 + tx;
        float v = t[tx][ty + i * 8];
        __nv_bfloat16 hi = __float2bfloat16(v);
        __nv_bfloat16 lo = __float2bfloat16(v - __bfloat162float(hi));
        g_whiT[o * KC + q] = hi;
        g_wloT[o * KC + q] = lo;
    }
}

// ---------------- GEMM1 (SIMT fp32, ascending-k): hid = relu(xin @ W1 + b1) ----------------
__global__ void __launch_bounds__(256) k_gemm1_s(const float* __restrict__ x,
                                                 const float* __restrict__ W1,
                                                 const float* __restrict__ b1) {
    __shared__ __align__(16) float As[32][132];
    __shared__ __align__(16) float Bs[32][68];
    int jn = blockIdx.x * 64;
    int pm = blockIdx.y * 128;
    int tid = threadIdx.x;
    int b = pm >> 12;
    int ty = tid >> 4, tx = tid & 15;
    float acc[8][4] = {};
    for (int c = 0; c < 5; c++) {
        int k0 = c * 32;
#pragma unroll
        for (int s = 0; s < 16; s++) {
            int t = tid + s * 256;
            int pl = t & 127, il = t >> 7;
            int i = k0 + il;
            int hw = (pm + pl) & 4095;
            float v;
            if (i < 128)        v = x[(b * CIN + i) * HWSZ + hw];
            else if (i == 128)  v = (float)(hw >> 6);
            else if (i == 129)  v = (float)(hw & 63);
            else                v = 0.f;
            As[il][pl] = v;
        }
#pragma unroll
        for (int s = 0; s < 8; s++) {
            int t = tid + s * 256;
            int jl = t & 63, il = t >> 6;
            int i = k0 + il;
            Bs[il][jl] = (i < 130) ? W1[i * 512 + jn + jl] : 0.f;
        }
        __syncthreads();
#pragma unroll
        for (int kk = 0; kk < 32; kk++) {
            float4 a0 = *(const float4*)&As[kk][ty * 8];
            float4 a1 = *(const float4*)&As[kk][ty * 8 + 4];
            float4 b4 = *(const float4*)&Bs[kk][tx * 4];
            float av[8] = {a0.x, a0.y, a0.z, a0.w, a1.x, a1.y, a1.z, a1.w};
            float bv[4] = {b4.x, b4.y, b4.z, b4.w};
#pragma unroll
            for (int m = 0; m < 8; m++)
#pragma unroll
                for (int n = 0; n < 4; n++) acc[m][n] += av[m] * bv[n];
        }
        __syncthreads();
    }
#pragma unroll
    for (int m = 0; m < 8; m++) {
        int p = pm + ty * 8 + m;
#pragma unroll
        for (int n = 0; n < 4; n++) {
            int j = jn + tx * 4 + n;
            float v = acc[m][n] + b1[j];
            g_hid[(size_t)p * HID + j] = v > 0.f ? v : 0.f;
        }
    }
}

// ---------------- GEMM2 (SIMT fp32, ascending-i, transposed-W2 smem, unrolled) ----------------
// Per-output scalar FMA chain identical to R13 (ascending i): params bitwise unchanged.
#define G2_SMEM (27 * 516 * 4)    // 55728 B

__global__ void __launch_bounds__(256) k_gemm2_t(const float* __restrict__ W2,
                                                 const float* __restrict__ b2) {
    extern __shared__ float W2T[];    // [27][516]
    int tid = threadIdx.x;
    for (int t = tid; t < 27 * 512; t += 256) {
        int i = t / 27, j = t - i * 27;            // coalesced global read
        W2T[j * 516 + i] = W2[t];
    }
    __syncthreads();
    int pl = tid >> 3, js = tid & 7;
    int p = blockIdx.x * 32 + pl;
    const float4* h4 = (const float4*)(g_hid + (size_t)p * HID);
    const float4* w0r = (const float4*)(W2T + js * 516);
    const float4* w1r = (const float4*)(W2T + (js + 8) * 516);
    const float4* w2r = (const float4*)(W2T + (js + 16) * 516);
    const float4* w3r = (const float4*)(W2T + (js + 24) * 516);   // valid only js<3
    bool has3 = js < 3;
    float acc0 = 0, acc1 = 0, acc2 = 0, acc3 = 0;
#pragma unroll 4
    for (int i4 = 0; i4 < 128; i4++) {
        float4 h = h4[i4];
        float4 w0 = w0r[i4];
        float4 w1 = w1r[i4];
        float4 w2 = w2r[i4];
        acc0 += h.x * w0.x; acc0 += h.y * w0.y; acc0 += h.z * w0.z; acc0 += h.w * w0.w;
        acc1 += h.x * w1.x; acc1 += h.y * w1.y; acc1 += h.z * w1.z; acc1 += h.w * w1.w;
        acc2 += h.x * w2.x; acc2 += h.y * w2.y; acc2 += h.z * w2.z; acc2 += h.w * w2.w;
        if (has3) {
            float4 w3 = w3r[i4];
            acc3 += h.x * w3.x; acc3 += h.y * w3.y; acc3 += h.z * w3.z; acc3 += h.w * w3.w;
        }
    }
    g_params[p * 27 + js]      = acc0 + b2[js];
    g_params[p * 27 + js + 8]  = acc1 + b2[js + 8];
    g_params[p * 27 + js + 16] = acc2 + b2[js + 16];
    if (has3) g_params[p * 27 + js + 24] = acc3 + b2[js + 24];
}

// ---------------- index generation + weights, one thread per (p,k) ----------------
__global__ void k_genidx(const float* __restrict__ mvalues,
                         uint32_t kg0, uint32_t kg1, uint32_t kr0, uint32_t kr1) {
    int gid = blockIdx.x * 256 + threadIdx.x;
    if (gid >= PTOT * KG) return;
    int p = gid / 9, k = gid - p * 9;
    int h = (p >> 6) & 63, w = p & 63;
    const float* pp = g_params + p * 27;
    float m0 = pp[2 * k], m1 = pp[2 * k + 1], sraw = pp[18 + k];
    float prh = fminf(fmaxf(h / 63.f, 1e-7f), 1.f - 1e-7f);
    float prw = fminf(fmaxf(w / 63.f, 1e-7f), 1.f - 1e-7f);
    float midr = logf(prh) - log1pf(-prh);
    float midc = logf(prw) - log1pf(-prw);
    float mr = 63.f / (1.f + expf(-(midr + m0)));
    float mc = 63.f / (1.f + expf(-(midc + m1)));
    float t = sraw + 2.f;
    float sp = fmaxf(t, 0.f) + log1pf(expf(-fabsf(t)));
    float sig = (sp + 0.05f) * 6.4f;
    float flr = floorf(mr), flc = floorf(mc);
    float fr[8], fc[8];
    fr[0] = flr;       fc[0] = flc;
    fr[1] = flr;       fc[1] = flc + 1.f;
    fr[2] = flr + 1.f; fc[2] = flc;
    fr[3] = flr + 1.f; fc[3] = flc + 1.f;
    uint32_t jb = (uint32_t)gid * 4u;
    fr[4] = (float)(jbits32(kg0, kg1, jb + 0) & 63u);
    fc[4] = (float)(jbits32(kg0, kg1, jb + 1) & 63u);
    fr[5] = (float)(jbits32(kg0, kg1, jb + 2) & 63u);
    fc[5] = (float)(jbits32(kg0, kg1, jb + 3) & 63u);
    fr[6] = flr - 4.f + (float)(jbits32(kr0, kr1, jb + 0) & 7u);
    fc[6] = flc - 4.f + (float)(jbits32(kr0, kr1, jb + 1) & 7u);
    fr[7] = flr - 4.f + (float)(jbits32(kr0, kr1, jb + 2) & 7u);
    fc[7] = flc - 4.f + (float)(jbits32(kr0, kr1, jb + 3) & 7u);
    int fl[8];
    float prv[8];
    float sum = 0.f;
#pragma unroll
    for (int v = 0; v < 8; v++) {
        float r = fminf(fmaxf(fr[v], 0.f), 63.f);
        float c = fminf(fmaxf(fc[v], 0.f), 63.f);
        int ri = (int)r, ci = (int)c;
        fl[v] = ri * 64 + ci;
        float zr = ((float)ri - mr) / sig;
        float zc = ((float)ci - mc) / sig;
        float pv = expf(-0.5f * (zr * zr + zc * zc));
        bool dup = false;
#pragma unroll
        for (int u = 0; u < 8; u++)
            if (u < v) dup |= (fl[u] == fl[v]);
        if (dup) pv = 0.f;
        prv[v] = pv;
        sum += pv;
    }
    float inv = mvalues[k] / (sum + 1e-7f);
    int base = gid * 8;
#pragma unroll
    for (int v = 0; v < 8; v++) {
        g_flat[base + v] = fl[v];
        g_wgt[base + v]  = prv[v] * inv;
    }
}

// ---------------- gather + weighted reduce -> bf16 hi/lo planes ----------------
__global__ void k_gather() {
    int wid  = (blockIdx.x * 256 + threadIdx.x) >> 5;
    int lane = threadIdx.x & 31;
    int p = wid / 9, k = wid - p * 9;
    int b = p >> 12;
    int base = wid * 8;
    int fi = 0; float wv = 0.f;
    if (lane < 8) { fi = g_flat[base + lane]; wv = g_wgt[base + lane]; }
    float4 acc = {0.f, 0.f, 0.f, 0.f};
    const float4* xb = (const float4*)(g_xt + (size_t)b * HWSZ * CIN);
#pragma unroll
    for (int v = 0; v < 8; v++) {
        int   f = __shfl_sync(0xffffffffu, fi, v);
        float g = __shfl_sync(0xffffffffu, wv, v);
        float4 xv = xb[f * 32 + lane];
        acc.x += g * xv.x; acc.y += g * xv.y; acc.z += g * xv.z; acc.w += g * xv.w;
    }
    float a[4] = {acc.x, acc.y, acc.z, acc.w};
    uint32_t hi2[2], lo2[2];
#pragma unroll
    for (int j = 0; j < 2; j++) {
        __nv_bfloat16 h0 = __float2bfloat16(a[2 * j]);
        __nv_bfloat16 h1 = __float2bfloat16(a[2 * j + 1]);
        __nv_bfloat16 l0 = __float2bfloat16(a[2 * j]     - __bfloat162float(h0));
        __nv_bfloat16 l1 = __float2bfloat16(a[2 * j + 1] - __bfloat162float(h1));
        hi2[j] = (uint32_t)__bfloat16_as_ushort(h0) | ((uint32_t)__bfloat16_as_ushort(h1) << 16);
        lo2[j] = (uint32_t)__bfloat16_as_ushort(l0) | ((uint32_t)__bfloat16_as_ushort(l1) << 16);
    }
    size_t off = (size_t)p * KC + k * 128 + lane * 4;
    *(uint2*)(g_fhi + off) = make_uint2(hi2[0], hi2[1]);
    *(uint2*)(g_flo + off) = make_uint2(lo2[0], lo2[1]);
}

// ---------------- GEMM3 (mma.sync bf16 3-split, 3-stage pipeline) ----------------
#define S3_AH 0
#define S3_AL 10240
#define S3_BH 20480
#define S3_BL 25600
#define S3_STG 30720
#define S3_SZ  92160

__global__ void __launch_bounds__(256, 2) k_gemm3_mma(const float* __restrict__ bu,
                                                      float* __restrict__ out) {
    extern __shared__ char smem[];
    uint32_t sb = smem_u32(smem);
    int tid = threadIdx.x;
    int wid = tid >> 5, lane = tid & 31;
    int wm = wid & 3, wn = wid >> 2;            // warp grid 4 (M) x 2 (N)
    int on = blockIdx.x * 64;
    int pm = blockIdx.y * 128;

    const __nv_bfloat16* Ah = g_fhi + (size_t)pm * KC;
    const __nv_bfloat16* Al = g_flo + (size_t)pm * KC;
    const __nv_bfloat16* Bh = g_whiT + (size_t)on * KC;
    const __nv_bfloat16* Bl = g_wloT + (size_t)on * KC;

    auto load_stage = [&](int stg, int koff) {
        uint32_t base = sb + stg * S3_STG;
#pragma unroll
        for (int t = tid; t < 512; t += 256) {
            int row = t >> 2, ch = t & 3;
            size_t go = (size_t)row * KC + koff + ch * 8;
            uint32_t sa = base + row * 80 + ch * 16;
            cpa16(sa + S3_AH, Ah + go);
            cpa16(sa + S3_AL, Al + go);
        }
        {
            int t = tid;
            if (t < 256) {
                int row = t >> 2, ch = t & 3;
                size_t go = (size_t)row * KC + koff + ch * 8;
                uint32_t sa = base + row * 80 + ch * 16;
                cpa16(sa + S3_BH, Bh + go);
                cpa16(sa + S3_BL, Bl + go);
            }
        }
    };

    float acc[2][4][4] = {};

    load_stage(0, 0);
    CP_COMMIT();
    load_stage(1, 32);
    CP_COMMIT();

    for (int c = 0; c < 36; c++) {
        if (c + 2 < 36) { load_stage((c + 2) % 3, (c + 2) * 32); CP_COMMIT(); CP_WAIT2(); }
        else if (c + 1 < 36) { CP_WAIT1(); }
        else { CP_WAIT0(); }
        __syncthreads();

        uint32_t base = sb + (c % 3) * S3_STG;
#pragma unroll
        for (int ks = 0; ks < 2; ks++) {
            int k0 = ks * 16;
            uint32_t ah[2][4], al[2][4], bh[2][4], bl[2][4];
#pragma unroll
            for (int mf = 0; mf < 2; mf++) {
                int r = wm * 32 + mf * 16 + (lane & 15);
                uint32_t ka = k0 + ((lane >> 4) << 3);
                uint32_t adr = base + r * 80 + ka * 2;
                ldsm4(ah[mf], adr + S3_AH);
                ldsm4(al[mf], adr + S3_AL);
            }
#pragma unroll
            for (int nh = 0; nh < 2; nh++) {
                int n = wn * 32 + nh * 16 + (lane & 7) + ((lane >> 4) << 3);
                uint32_t kb = k0 + (((lane >> 3) & 1) << 3);
                uint32_t adr = base + n * 80 + kb * 2;
                ldsm4(bh[nh], adr + S3_BH);
                ldsm4(bl[nh], adr + S3_BL);
            }
#pragma unroll
            for (int mf = 0; mf < 2; mf++)
#pragma unroll
                for (int nf = 0; nf < 4; nf++) {
                    int nh = nf >> 1, j = (nf & 1) * 2;
                    mma_bf16(acc[mf][nf], ah[mf], bh[nh][j], bh[nh][j + 1]);
                    mma_bf16(acc[mf][nf], ah[mf], bl[nh][j], bl[nh][j + 1]);
                    mma_bf16(acc[mf][nf], al[mf], bh[nh][j], bh[nh][j + 1]);
                }
        }
        __syncthreads();
    }

#pragma unroll
    for (int mf = 0; mf < 2; mf++) {
        int p0 = pm + wm * 32 + mf * 16 + (lane >> 2);
        int b = p0 >> 12;
        int hw0 = p0 & 4095;
        int hw1 = hw0 + 8;
#pragma unroll
        for (int nf = 0; nf < 4; nf++) {
            int o = on + wn * 32 + nf * 8 + (lane & 3) * 2;
            float bv0 = bu[o], bv1 = bu[o + 1];
            float* c0 = out + (((size_t)(b * COUT + o)) << 12);
            float* c1 = out + (((size_t)(b * COUT + o + 1)) << 12);
            c0[hw0] = acc[mf][nf][0] + bv0;
            c1[hw0] = acc[mf][nf][1] + bv1;
            c0[hw1] = acc[mf][nf][2] + bv0;
            c1[hw1] = acc[mf][nf][3] + bv1;
        }
    }
}

// ---------------- launch ----------------
extern "C" void kernel_launch(void* const* d_in, const int* in_sizes, int n_in,
                              void* d_out, int out_size) {
    const float* x   = (const float*)d_in[0];
    const float* W1  = (const float*)d_in[1];
    const float* b1  = (const float*)d_in[2];
    const float* W2  = (const float*)d_in[3];
    const float* b2  = (const float*)d_in[4];
    const float* Wu  = (const float*)d_in[5];
    const float* bu  = (const float*)d_in[6];
    const float* mv  = (const float*)d_in[7];
    float* out = (float*)d_out;

    // jax_threefry_partitionable: split(key) child i = threefry(key, 0, i)
    uint32_t kg0, kg1, kr0, kr1;
    threefry(0u, 12345u, 0u, 0u, kg0, kg1);   // kg = split(base)[0]
    threefry(0u, 12345u, 0u, 1u, kr0, kr1);   // kr = split(base)[1]
    // randint: k1,k2 = split(key); pow2 span => lower_bits(k2) % span
    uint32_t kg2_0, kg2_1, kr2_0, kr2_1;
    threefry(kg0, kg1, 0u, 1u, kg2_0, kg2_1); // split(kg)[1]
    threefry(kr0, kr1, 0u, 1u, kr2_0, kr2_1); // split(kr)[1]

    cudaFuncSetAttribute(k_gemm2_t, cudaFuncAttributeMaxDynamicSharedMemorySize, G2_SMEM);
    cudaFuncSetAttribute(k_gemm3_mma, cudaFuncAttributeMaxDynamicSharedMemorySize, S3_SZ);

    k_transpose<<<dim3(128, 4, 4), dim3(32, 8)>>>(x);
    k_wuprep<<<dim3(36, 8), dim3(32, 8)>>>(Wu);
    k_gemm1_s<<<dim3(8, 128), 256>>>(x, W1, b1);
    k_gemm2_t<<<512, 256, G2_SMEM>>>(W2, b2);
    k_genidx<<<576, 256>>>(mv, kg2_0, kg2_1, kr2_0, kr2_1);
    k_gather<<<18432, 256>>>();
    k_gemm3_mma<<<dim3(4, 128), 256, S3_SZ>>>(bu, out);
}

// round 15
// speedup vs baseline: 1.0518x; 1.0518x over previous
#include <cuda_runtime.h>
#include <cuda_bf16.h>
#include <cstdint>

#define BB   4
#define CIN  128
#define COUT 256
#define HWSZ 4096
#define PTOT 16384
#define KG   9
#define HID  512
#define KC   1152

// ---------------- threefry2x32 (jax-compatible) ----------------
__host__ __device__ __forceinline__ uint32_t rotl32(uint32_t x, int d) {
    return (x << d) | (x >> (32 - d));
}
__host__ __device__ __forceinline__ void threefry(uint32_t k0, uint32_t k1,
                                                  uint32_t x0, uint32_t x1,
                                                  uint32_t& o0, uint32_t& o1) {
    uint32_t ks2 = k0 ^ k1 ^ 0x1BD11BDAu;
    x0 += k0; x1 += k1;
#define TFR(r) { x0 += x1; x1 = rotl32(x1, r); x1 ^= x0; }
    TFR(13) TFR(15) TFR(26) TFR(6)
    x0 += k1;  x1 += ks2 + 1u;
    TFR(17) TFR(29) TFR(16) TFR(24)
    x0 += ks2; x1 += k0 + 2u;
    TFR(13) TFR(15) TFR(26) TFR(6)
    x0 += k0;  x1 += k1 + 3u;
    TFR(17) TFR(29) TFR(16) TFR(24)
    x0 += k1;  x1 += ks2 + 4u;
    TFR(13) TFR(15) TFR(26) TFR(6)
    x0 += ks2; x1 += k0 + 5u;
#undef TFR
    o0 = x0; o1 = x1;
}

// partitionable-threefry 32-bit sample for flat element i: sample = o0 ^ o1
__device__ __forceinline__ uint32_t jbits32(uint32_t k0, uint32_t k1, uint32_t i) {
    uint32_t o0, o1;
    threefry(k0, k1, 0u, i, o0, o1);
    return o0 ^ o1;
}

// ---------------- baseline-ISA asm helpers ----------------
__device__ __forceinline__ uint32_t smem_u32(const void* p) {
    uint32_t a;
    asm("{ .reg .u64 t; cvta.to.shared.u64 t, %1; cvt.u32.u64 %0, t; }" : "=r"(a) : "l"(p));
    return a;
}
__device__ __forceinline__ void cpa16(uint32_t sa, const void* g) {
    asm volatile("cp.async.cg.shared.global [%0], [%1], 16;" :: "r"(sa), "l"(g));
}
#define CP_COMMIT() asm volatile("cp.async.commit_group;" ::: "memory")
#define CP_WAIT1()  asm volatile("cp.async.wait_group 1;" ::: "memory")
#define CP_WAIT0()  asm volatile("cp.async.wait_group 0;" ::: "memory")

__device__ __forceinline__ void ldsm4(uint32_t* r, uint32_t addr) {
    asm volatile("ldmatrix.sync.aligned.m8n8.x4.shared.b16 {%0,%1,%2,%3}, [%4];"
        : "=r"(r[0]), "=r"(r[1]), "=r"(r[2]), "=r"(r[3]) : "r"(addr));
}
__device__ __forceinline__ void mma_bf16(float* c, const uint32_t* a, uint32_t b0, uint32_t b1) {
    asm volatile("mma.sync.aligned.m16n8k16.row.col.f32.bf16.bf16.f32 "
        "{%0,%1,%2,%3}, {%4,%5,%6,%7}, {%8,%9}, {%0,%1,%2,%3};"
        : "+f"(c[0]), "+f"(c[1]), "+f"(c[2]), "+f"(c[3])
        : "r"(a[0]), "r"(a[1]), "r"(a[2]), "r"(a[3]), "r"(b0), "r"(b1));
}

// ---------------- scratch (device globals; no allocs allowed) ----------------
__device__ float g_xt[BB * HWSZ * CIN];           // x transposed: [b][hw][c]
__device__ float g_hid[PTOT * HID];               // hidden layer
__device__ float g_params[PTOT * 27];             // MLP output
__device__ int   g_flat[PTOT * KG * 8];           // candidate flat indices
__device__ float g_wgt[PTOT * KG * 8];            // candidate weights
__device__ __nv_bfloat16 g_fhi[(size_t)PTOT * KC];  // feat hi (bf16)
__device__ __nv_bfloat16 g_flo[(size_t)PTOT * KC];  // feat lo (bf16)
__device__ __nv_bfloat16 g_whiT[COUT * KC];       // Wu^T hi: [o][q]
__device__ __nv_bfloat16 g_wloT[COUT * KC];       // Wu^T lo: [o][q]

// ---------------- x transpose: (b,c,hw) -> (b,hw,c) ----------------
__global__ void k_transpose(const float* __restrict__ x) {
    __shared__ float tile[32][33];
    int b = blockIdx.z;
    int hw0 = blockIdx.x * 32, c0 = blockIdx.y * 32;
    int tx = threadIdx.x, ty = threadIdx.y;   // 32 x 8
#pragma unroll
    for (int i = 0; i < 4; i++) {
        int c = c0 + ty + i * 8;
        tile[ty + i * 8][tx] = x[(b * CIN + c) * HWSZ + hw0 + tx];
    }
    __syncthreads();
#pragma unroll
    for (int i = 0; i < 4; i++) {
        int hw = hw0 + ty + i * 8;
        g_xt[(b * HWSZ + hw) * CIN + c0 + tx] = tile[tx][ty + i * 8];
    }
}

// ---------------- Wu transpose + bf16 split ----------------
__global__ void k_wuprep(const float* __restrict__ Wu) {
    __shared__ float t[32][33];
    int q0 = blockIdx.x * 32, o0 = blockIdx.y * 32;
    int tx = threadIdx.x, ty = threadIdx.y;   // 32 x 8
#pragma unroll
    for (int i = 0; i < 4; i++)
        t[ty + i * 8][tx] = Wu[(q0 + ty + i * 8) * COUT + o0 + tx];
    __syncthreads();
#pragma unroll
    for (int i = 0; i < 4; i++) {
        int o = o0 + ty + i * 8, q = q0 + tx;
        float v = t[tx][ty + i * 8];
        __nv_bfloat16 hi = __float2bfloat16(v);
        __nv_bfloat16 lo = __float2bfloat16(v - __bfloat162float(hi));
        g_whiT[o * KC + q] = hi;
        g_wloT[o * KC + q] = lo;
    }
}

// ---------------- GEMM1 (SIMT fp32, ascending-k): hid = relu(xin @ W1 + b1) ----------------
__global__ void __launch_bounds__(256) k_gemm1_s(const float* __restrict__ x,
                                                 const float* __restrict__ W1,
                                                 const float* __restrict__ b1) {
    __shared__ __align__(16) float As[32][132];
    __shared__ __align__(16) float Bs[32][68];
    int jn = blockIdx.x * 64;
    int pm = blockIdx.y * 128;
    int tid = threadIdx.x;
    int b = pm >> 12;
    int ty = tid >> 4, tx = tid & 15;
    float acc[8][4] = {};
    for (int c = 0; c < 5; c++) {
        int k0 = c * 32;
#pragma unroll
        for (int s = 0; s < 16; s++) {
            int t = tid + s * 256;
            int pl = t & 127, il = t >> 7;
            int i = k0 + il;
            int hw = (pm + pl) & 4095;
            float v;
            if (i < 128)        v = x[(b * CIN + i) * HWSZ + hw];
            else if (i == 128)  v = (float)(hw >> 6);
            else if (i == 129)  v = (float)(hw & 63);
            else                v = 0.f;
            As[il][pl] = v;
        }
#pragma unroll
        for (int s = 0; s < 8; s++) {
            int t = tid + s * 256;
            int jl = t & 63, il = t >> 6;
            int i = k0 + il;
            Bs[il][jl] = (i < 130) ? W1[i * 512 + jn + jl] : 0.f;
        }
        __syncthreads();
#pragma unroll
        for (int kk = 0; kk < 32; kk++) {
            float4 a0 = *(const float4*)&As[kk][ty * 8];
            float4 a1 = *(const float4*)&As[kk][ty * 8 + 4];
            float4 b4 = *(const float4*)&Bs[kk][tx * 4];
            float av[8] = {a0.x, a0.y, a0.z, a0.w, a1.x, a1.y, a1.z, a1.w};
            float bv[4] = {b4.x, b4.y, b4.z, b4.w};
#pragma unroll
            for (int m = 0; m < 8; m++)
#pragma unroll
                for (int n = 0; n < 4; n++) acc[m][n] += av[m] * bv[n];
        }
        __syncthreads();
    }
#pragma unroll
    for (int m = 0; m < 8; m++) {
        int p = pm + ty * 8 + m;
#pragma unroll
        for (int n = 0; n < 4; n++) {
            int j = jn + tx * 4 + n;
            float v = acc[m][n] + b1[j];
            g_hid[(size_t)p * HID + j] = v > 0.f ? v : 0.f;
        }
    }
}

// ---------------- GEMM2 (SIMT fp32, 4 pixels/thread, transposed-W2 smem) ----------------
// Weights amortized over 4 pixels; per-output FMA chain unchanged (ascending i).
#define G2_SMEM (27 * 516 * 4)    // 55728 B

__global__ void __launch_bounds__(256) k_gemm2_q(const float* __restrict__ W2,
                                                 const float* __restrict__ b2) {
    extern __shared__ float W2T[];    // [27][516]
    int tid = threadIdx.x;
    for (int t = tid; t < 27 * 512; t += 256) {
        int i = t / 27, j = t - i * 27;            // coalesced global read
        W2T[j * 516 + i] = W2[t];
    }
    __syncthreads();
    int pg = tid >> 3, js = tid & 7;
    int p0 = blockIdx.x * 128 + pg * 4;
    const float4* hp0 = (const float4*)(g_hid + (size_t)p0 * HID);
    const float4* hp1 = (const float4*)(g_hid + (size_t)(p0 + 1) * HID);
    const float4* hp2 = (const float4*)(g_hid + (size_t)(p0 + 2) * HID);
    const float4* hp3 = (const float4*)(g_hid + (size_t)(p0 + 3) * HID);
    const float4* w0r = (const float4*)(W2T + js * 516);
    const float4* w1r = (const float4*)(W2T + (js + 8) * 516);
    const float4* w2r = (const float4*)(W2T + (js + 16) * 516);
    const float4* w3r = (const float4*)(W2T + (js + 24) * 516);   // valid only js<3
    bool has3 = js < 3;
    float a0[4] = {}, a1[4] = {}, a2[4] = {}, a3[4] = {};
    for (int i4 = 0; i4 < 128; i4++) {
        float4 w0 = w0r[i4];
        float4 w1 = w1r[i4];
        float4 w2 = w2r[i4];
        float4 w3 = make_float4(0.f, 0.f, 0.f, 0.f);
        if (has3) w3 = w3r[i4];
        float4 h;
        h = hp0[i4];
        a0[0] += h.x * w0.x; a0[0] += h.y * w0.y; a0[0] += h.z * w0.z; a0[0] += h.w * w0.w;
        a1[0] += h.x * w1.x; a1[0] += h.y * w1.y; a1[0] += h.z * w1.z; a1[0] += h.w * w1.w;
        a2[0] += h.x * w2.x; a2[0] += h.y * w2.y; a2[0] += h.z * w2.z; a2[0] += h.w * w2.w;
        if (has3) { a3[0] += h.x * w3.x; a3[0] += h.y * w3.y; a3[0] += h.z * w3.z; a3[0] += h.w * w3.w; }
        h = hp1[i4];
        a0[1] += h.x * w0.x; a0[1] += h.y * w0.y; a0[1] += h.z * w0.z; a0[1] += h.w * w0.w;
        a1[1] += h.x * w1.x; a1[1] += h.y * w1.y; a1[1] += h.z * w1.z; a1[1] += h.w * w1.w;
        a2[1] += h.x * w2.x; a2[1] += h.y * w2.y; a2[1] += h.z * w2.z; a2[1] += h.w * w2.w;
        if (has3) { a3[1] += h.x * w3.x; a3[1] += h.y * w3.y; a3[1] += h.z * w3.z; a3[1] += h.w * w3.w; }
        h = hp2[i4];
        a0[2] += h.x * w0.x; a0[2] += h.y * w0.y; a0[2] += h.z * w0.z; a0[2] += h.w * w0.w;
        a1[2] += h.x * w1.x; a1[2] += h.y * w1.y; a1[2] += h.z * w1.z; a1[2] += h.w * w1.w;
        a2[2] += h.x * w2.x; a2[2] += h.y * w2.y; a2[2] += h.z * w2.z; a2[2] += h.w * w2.w;
        if (has3) { a3[2] += h.x * w3.x; a3[2] += h.y * w3.y; a3[2] += h.z * w3.z; a3[2] += h.w * w3.w; }
        h = hp3[i4];
        a0[3] += h.x * w0.x; a0[3] += h.y * w0.y; a0[3] += h.z * w0.z; a0[3] += h.w * w0.w;
        a1[3] += h.x * w1.x; a1[3] += h.y * w1.y; a1[3] += h.z * w1.z; a1[3] += h.w * w1.w;
        a2[3] += h.x * w2.x; a2[3] += h.y * w2.y; a2[3] += h.z * w2.z; a2[3] += h.w * w2.w;
        if (has3) { a3[3] += h.x * w3.x; a3[3] += h.y * w3.y; a3[3] += h.z * w3.z; a3[3] += h.w * w3.w; }
    }
#pragma unroll
    for (int px = 0; px < 4; px++) {
        int p = p0 + px;
        g_params[p * 27 + js]      = a0[px] + b2[js];
        g_params[p * 27 + js + 8]  = a1[px] + b2[js + 8];
        g_params[p * 27 + js + 16] = a2[px] + b2[js + 16];
        if (has3) g_params[p * 27 + js + 24] = a3[px] + b2[js + 24];
    }
}

// ---------------- index generation + weights, one thread per (p,k) ----------------
__global__ void k_genidx(const float* __restrict__ mvalues,
                         uint32_t kg0, uint32_t kg1, uint32_t kr0, uint32_t kr1) {
    int gid = blockIdx.x * 256 + threadIdx.x;
    if (gid >= PTOT * KG) return;
    int p = gid / 9, k = gid - p * 9;
    int h = (p >> 6) & 63, w = p & 63;
    const float* pp = g_params + p * 27;
    float m0 = pp[2 * k], m1 = pp[2 * k + 1], sraw = pp[18 + k];
    float prh = fminf(fmaxf(h / 63.f, 1e-7f), 1.f - 1e-7f);
    float prw = fminf(fmaxf(w / 63.f, 1e-7f), 1.f - 1e-7f);
    float midr = logf(prh) - log1pf(-prh);
    float midc = logf(prw) - log1pf(-prw);
    float mr = 63.f / (1.f + expf(-(midr + m0)));
    float mc = 63.f / (1.f + expf(-(midc + m1)));
    float t = sraw + 2.f;
    float sp = fmaxf(t, 0.f) + log1pf(expf(-fabsf(t)));
    float sig = (sp + 0.05f) * 6.4f;
    float flr = floorf(mr), flc = floorf(mc);
    float fr[8], fc[8];
    fr[0] = flr;       fc[0] = flc;
    fr[1] = flr;       fc[1] = flc + 1.f;
    fr[2] = flr + 1.f; fc[2] = flc;
    fr[3] = flr + 1.f; fc[3] = flc + 1.f;
    uint32_t jb = (uint32_t)gid * 4u;
    fr[4] = (float)(jbits32(kg0, kg1, jb + 0) & 63u);
    fc[4] = (float)(jbits32(kg0, kg1, jb + 1) & 63u);
    fr[5] = (float)(jbits32(kg0, kg1, jb + 2) & 63u);
    fc[5] = (float)(jbits32(kg0, kg1, jb + 3) & 63u);
    fr[6] = flr - 4.f + (float)(jbits32(kr0, kr1, jb + 0) & 7u);
    fc[6] = flc - 4.f + (float)(jbits32(kr0, kr1, jb + 1) & 7u);
    fr[7] = flr - 4.f + (float)(jbits32(kr0, kr1, jb + 2) & 7u);
    fc[7] = flc - 4.f + (float)(jbits32(kr0, kr1, jb + 3) & 7u);
    int fl[8];
    float prv[8];
    float sum = 0.f;
#pragma unroll
    for (int v = 0; v < 8; v++) {
        float r = fminf(fmaxf(fr[v], 0.f), 63.f);
        float c = fminf(fmaxf(fc[v], 0.f), 63.f);
        int ri = (int)r, ci = (int)c;
        fl[v] = ri * 64 + ci;
        float zr = ((float)ri - mr) / sig;
        float zc = ((float)ci - mc) / sig;
        float pv = expf(-0.5f * (zr * zr + zc * zc));
        bool dup = false;
#pragma unroll
        for (int u = 0; u < 8; u++)
            if (u < v) dup |= (fl[u] == fl[v]);
        if (dup) pv = 0.f;
        prv[v] = pv;
        sum += pv;
    }
    float inv = mvalues[k] / (sum + 1e-7f);
    int base = gid * 8;
#pragma unroll
    for (int v = 0; v < 8; v++) {
        g_flat[base + v] = fl[v];
        g_wgt[base + v]  = prv[v] * inv;
    }
}

// ---------------- gather + weighted reduce -> bf16 hi/lo planes ----------------
__global__ void k_gather() {
    int wid  = (blockIdx.x * 256 + threadIdx.x) >> 5;
    int lane = threadIdx.x & 31;
    int p = wid / 9, k = wid - p * 9;
    int b = p >> 12;
    int base = wid * 8;
    int fi = 0; float wv = 0.f;
    if (lane < 8) { fi = g_flat[base + lane]; wv = g_wgt[base + lane]; }
    float4 acc = {0.f, 0.f, 0.f, 0.f};
    const float4* xb = (const float4*)(g_xt + (size_t)b * HWSZ * CIN);
#pragma unroll
    for (int v = 0; v < 8; v++) {
        int   f = __shfl_sync(0xffffffffu, fi, v);
        float g = __shfl_sync(0xffffffffu, wv, v);
        float4 xv = xb[f * 32 + lane];
        acc.x += g * xv.x; acc.y += g * xv.y; acc.z += g * xv.z; acc.w += g * xv.w;
    }
    float a[4] = {acc.x, acc.y, acc.z, acc.w};
    uint32_t hi2[2], lo2[2];
#pragma unroll
    for (int j = 0; j < 2; j++) {
        __nv_bfloat16 h0 = __float2bfloat16(a[2 * j]);
        __nv_bfloat16 h1 = __float2bfloat16(a[2 * j + 1]);
        __nv_bfloat16 l0 = __float2bfloat16(a[2 * j]     - __bfloat162float(h0));
        __nv_bfloat16 l1 = __float2bfloat16(a[2 * j + 1] - __bfloat162float(h1));
        hi2[j] = (uint32_t)__bfloat16_as_ushort(h0) | ((uint32_t)__bfloat16_as_ushort(h1) << 16);
        lo2[j] = (uint32_t)__bfloat16_as_ushort(l0) | ((uint32_t)__bfloat16_as_ushort(l1) << 16);
    }
    size_t off = (size_t)p * KC + k * 128 + lane * 4;
    *(uint2*)(g_fhi + off) = make_uint2(hi2[0], hi2[1]);
    *(uint2*)(g_flo + off) = make_uint2(lo2[0], lo2[1]);
}

// ---------------- GEMM3 (mma.sync bf16 3-split, 2-stage pipeline) ----------------
#define S3_AH 0
#define S3_AL 10240
#define S3_BH 20480
#define S3_BL 25600
#define S3_STG 30720
#define S3_SZ  61440

__global__ void __launch_bounds__(256, 2) k_gemm3_mma(const float* __restrict__ bu,
                                                      float* __restrict__ out) {
    extern __shared__ char smem[];
    uint32_t sb = smem_u32(smem);
    int tid = threadIdx.x;
    int wid = tid >> 5, lane = tid & 31;
    int wm = wid & 3, wn = wid >> 2;            // warp grid 4 (M) x 2 (N)
    int on = blockIdx.x * 64;
    int pm = blockIdx.y * 128;

    const __nv_bfloat16* Ah = g_fhi + (size_t)pm * KC;
    const __nv_bfloat16* Al = g_flo + (size_t)pm * KC;
    const __nv_bfloat16* Bh = g_whiT + (size_t)on * KC;
    const __nv_bfloat16* Bl = g_wloT + (size_t)on * KC;

    auto load_stage = [&](int stg, int koff) {
        uint32_t base = sb + stg * S3_STG;
#pragma unroll
        for (int t = tid; t < 512; t += 256) {
            int row = t >> 2, ch = t & 3;
            size_t go = (size_t)row * KC + koff + ch * 8;
            uint32_t sa = base + row * 80 + ch * 16;
            cpa16(sa + S3_AH, Ah + go);
            cpa16(sa + S3_AL, Al + go);
        }
        {
            int t = tid;
            if (t < 256) {
                int row = t >> 2, ch = t & 3;
                size_t go = (size_t)row * KC + koff + ch * 8;
                uint32_t sa = base + row * 80 + ch * 16;
                cpa16(sa + S3_BH, Bh + go);
                cpa16(sa + S3_BL, Bl + go);
            }
        }
    };

    float acc[2][4][4] = {};

    load_stage(0, 0);
    CP_COMMIT();

    for (int c = 0; c < 36; c++) {
        if (c + 1 < 36) { load_stage((c + 1) & 1, (c + 1) * 32); CP_COMMIT(); CP_WAIT1(); }
        else            { CP_WAIT0(); }
        __syncthreads();

        uint32_t base = sb + (c & 1) * S3_STG;
#pragma unroll
        for (int ks = 0; ks < 2; ks++) {
            int k0 = ks * 16;
            uint32_t ah[2][4], al[2][4], bh[2][4], bl[2][4];
#pragma unroll
            for (int mf = 0; mf < 2; mf++) {
                int r = wm * 32 + mf * 16 + (lane & 15);
                uint32_t ka = k0 + ((lane >> 4) << 3);
                uint32_t adr = base + r * 80 + ka * 2;
                ldsm4(ah[mf], adr + S3_AH);
                ldsm4(al[mf], adr + S3_AL);
            }
#pragma unroll
            for (int nh = 0; nh < 2; nh++) {
                int n = wn * 32 + nh * 16 + (lane & 7) + ((lane >> 4) << 3);
                uint32_t kb = k0 + (((lane >> 3) & 1) << 3);
                uint32_t adr = base + n * 80 + kb * 2;
                ldsm4(bh[nh], adr + S3_BH);
                ldsm4(bl[nh], adr + S3_BL);
            }
#pragma unroll
            for (int mf = 0; mf < 2; mf++)
#pragma unroll
                for (int nf = 0; nf < 4; nf++) {
                    int nh = nf >> 1, j = (nf & 1) * 2;
                    mma_bf16(acc[mf][nf], ah[mf], bh[nh][j], bh[nh][j + 1]);
                    mma_bf16(acc[mf][nf], ah[mf], bl[nh][j], bl[nh][j + 1]);
                    mma_bf16(acc[mf][nf], al[mf], bh[nh][j], bh[nh][j + 1]);
                }
        }
        __syncthreads();
    }

#pragma unroll
    for (int mf = 0; mf < 2; mf++) {
        int p0 = pm + wm * 32 + mf * 16 + (lane >> 2);
        int b = p0 >> 12;
        int hw0 = p0 & 4095;
        int hw1 = hw0 + 8;
#pragma unroll
        for (int nf = 0; nf < 4; nf++) {
            int o = on + wn * 32 + nf * 8 + (lane & 3) * 2;
            float bv0 = bu[o], bv1 = bu[o + 1];
            float* c0 = out + (((size_t)(b * COUT + o)) << 12);
            float* c1 = out + (((size_t)(b * COUT + o + 1)) << 12);
            c0[hw0] = acc[mf][nf][0] + bv0;
            c1[hw0] = acc[mf][nf][1] + bv1;
            c0[hw1] = acc[mf][nf][2] + bv0;
            c1[hw1] = acc[mf][nf][3] + bv1;
        }
    }
}

// ---------------- launch ----------------
extern "C" void kernel_launch(void* const* d_in, const int* in_sizes, int n_in,
                              void* d_out, int out_size) {
    const float* x   = (const float*)d_in[0];
    const float* W1  = (const float*)d_in[1];
    const float* b1  = (const float*)d_in[2];
    const float* W2  = (const float*)d_in[3];
    const float* b2  = (const float*)d_in[4];
    const float* Wu  = (const float*)d_in[5];
    const float* bu  = (const float*)d_in[6];
    const float* mv  = (const float*)d_in[7];
    float* out = (float*)d_out;

    // jax_threefry_partitionable: split(key) child i = threefry(key, 0, i)
    uint32_t kg0, kg1, kr0, kr1;
    threefry(0u, 12345u, 0u, 0u, kg0, kg1);   // kg = split(base)[0]
    threefry(0u, 12345u, 0u, 1u, kr0, kr1);   // kr = split(base)[1]
    // randint: k1,k2 = split(key); pow2 span => lower_bits(k2) % span
    uint32_t kg2_0, kg2_1, kr2_0, kr2_1;
    threefry(kg0, kg1, 0u, 1u, kg2_0, kg2_1); // split(kg)[1]
    threefry(kr0, kr1, 0u, 1u, kr2_0, kr2_1); // split(kr)[1]

    cudaFuncSetAttribute(k_gemm2_q, cudaFuncAttributeMaxDynamicSharedMemorySize, G2_SMEM);
    cudaFuncSetAttribute(k_gemm3_mma, cudaFuncAttributeMaxDynamicSharedMemorySize, S3_SZ);

    k_transpose<<<dim3(128, 4, 4), dim3(32, 8)>>>(x);
    k_wuprep<<<dim3(36, 8), dim3(32, 8)>>>(Wu);
    k_gemm1_s<<<dim3(8, 128), 256>>>(x, W1, b1);
    k_gemm2_q<<<128, 256, G2_SMEM>>>(W2, b2);
    k_genidx<<<576, 256>>>(mv, kg2_0, kg2_1, kr2_0, kr2_1);
    k_gather<<<18432, 256>>>();
    k_gemm3_mma<<<dim3(4, 128), 256, S3_SZ>>>(bu, out);
}